// round 10
// baseline (speedup 1.0000x reference)
#include <cuda_runtime.h>
#include <cuda_fp16.h>
#include <math.h>
#include <stdint.h>

#define BB   128
#define CF   1024
#define RR   256
#define NATT 312
#define DV   300
#define NI   624
#define NIP  640

// ---------------- scratch (device globals) ----------------
__device__ __half g_A[NIP * CF];               // interleaved [2i]=Q_i,[2i+1]=P_i
__device__ __half g_B[(size_t)BB * RR * CF];   // [b][r][k] RAW img (transposed), fp16
__device__ float  g_part[BB * 32 * RR];        // partial sumsq [b][kc][r]
__device__ float  g_inorm[BB * RR];            // 1 / max(||img[b,:,r]||, eps)

// ---------------- helpers ----------------
__device__ __forceinline__ uint32_t smem_u32(const void* p) {
    uint32_t a;
    asm("{ .reg .u64 t; cvta.to.shared.u64 t, %1; cvt.u32.u64 %0, t; }" : "=r"(a) : "l"(p));
    return a;
}
#define CP_ASYNC16(dst, src) \
    asm volatile("cp.async.cg.shared.global [%0], [%1], 16;" :: "r"(dst), "l"(src) : "memory")
#define CP_COMMIT() asm volatile("cp.async.commit_group;" ::: "memory")
#define CP_WAIT(N)  asm volatile("cp.async.wait_group %0;" :: "n"(N) : "memory")

__device__ __forceinline__ void ldsm4(uint32_t* r, uint32_t addr) {
    asm volatile("ldmatrix.sync.aligned.m8n8.x4.shared.b16 {%0,%1,%2,%3}, [%4];"
                 : "=r"(r[0]), "=r"(r[1]), "=r"(r[2]), "=r"(r[3]) : "r"(addr));
}
__device__ __forceinline__ void mma_fp16(float* c, const uint32_t* a, const uint32_t* b) {
    asm volatile(
        "mma.sync.aligned.m16n8k16.row.col.f32.f16.f16.f32 "
        "{%0,%1,%2,%3}, {%4,%5,%6,%7}, {%8,%9}, {%0,%1,%2,%3};"
        : "+f"(c[0]), "+f"(c[1]), "+f"(c[2]), "+f"(c[3])
        : "r"(a[0]), "r"(a[1]), "r"(a[2]), "r"(a[3]), "r"(b[0]), "r"(b[1]));
}

// ---------------------------------------------------------------------------
// 1) QP rows: normalize V rows, multiply by W, interleave, single fp16.
// ---------------------------------------------------------------------------
__global__ void __launch_bounds__(256) k_qp(const float* __restrict__ V,
                                            const float* __restrict__ W1,
                                            const float* __restrict__ W2) {
    int i0 = blockIdx.x * 16;
    int z  = blockIdx.z;
    int j  = blockIdx.y * 256 + threadIdx.x;
    const float* W = z ? W2 : W1;

    __shared__ float vrow[16][DV];
    for (int t = threadIdx.x; t < 16 * DV; t += 256) {
        int ii = t / DV, k = t % DV;
        int gi = i0 + ii;
        vrow[ii][k] = (gi < NATT) ? V[gi * DV + k] : 0.f;
    }
    __syncthreads();
    {
        int w = threadIdx.x >> 5, lane = threadIdx.x & 31;
#pragma unroll
        for (int h = 0; h < 2; h++) {
            int row = 2 * w + h;
            float s = 0.f;
            for (int k = lane; k < DV; k += 32) { float v = vrow[row][k]; s += v * v; }
#pragma unroll
            for (int off = 16; off; off >>= 1) s += __shfl_xor_sync(0xffffffffu, s, off);
            float inv = 1.f / fmaxf(sqrtf(s), 1e-12f);
            for (int k = lane; k < DV; k += 32) vrow[row][k] *= inv;
        }
    }
    __syncthreads();

    float acc[16];
#pragma unroll
    for (int ii = 0; ii < 16; ii++) acc[ii] = 0.f;
    for (int k = 0; k < DV; k++) {
        float w = W[k * CF + j];
#pragma unroll
        for (int ii = 0; ii < 16; ii++) acc[ii] += vrow[ii][k] * w;
    }
#pragma unroll
    for (int ii = 0; ii < 16; ii++) {
        int row = 2 * (i0 + ii) + z;
        g_A[row * CF + j] = __float2half(acc[ii]);
    }
}

// ---------------------------------------------------------------------------
// 2) Fused transpose+convert+norm-partials: ONE pass over img.
// ---------------------------------------------------------------------------
__global__ void __launch_bounds__(256) k_conv(const float* __restrict__ img) {
    int b  = blockIdx.x;
    int k0 = blockIdx.y * 32;
    int tid = threadIdx.x;
    __shared__ float t[32][257];
    const float* src = img + (size_t)b * CF * RR + (size_t)k0 * RR;
#pragma unroll 8
    for (int k = 0; k < 32; k++) t[k][tid] = src[k * RR + tid];
    __syncthreads();

    {
        float s = 0.f;
#pragma unroll
        for (int k = 0; k < 32; k++) { float v = t[k][tid]; s += v * v; }
        g_part[(b * 32 + blockIdx.y) * RR + tid] = s;
    }

    __half* dst = g_B + ((size_t)b * RR) * CF + k0;
#pragma unroll
    for (int it = 0; it < 8; it++) {
        int idx = it * 256 + tid;
        int r   = idx >> 3;
        int kk  = (idx & 7) * 4;
        __half2 h0 = __floats2half2_rn(t[kk + 0][r], t[kk + 1][r]);
        __half2 h1 = __floats2half2_rn(t[kk + 2][r], t[kk + 3][r]);
        __half2* p = (__half2*)(dst + (size_t)r * CF + kk);
        p[0] = h0;
        p[1] = h1;
    }
}

// ---------------------------------------------------------------------------
// 3) reduce partials -> inorm
// ---------------------------------------------------------------------------
__global__ void __launch_bounds__(256) k_nred() {
    int b = blockIdx.x, r = threadIdx.x;
    float s = 0.f;
#pragma unroll
    for (int kc = 0; kc < 32; kc++) s += g_part[(b * 32 + kc) * RR + r];
    g_inorm[b * RR + r] = 1.f / fmaxf(sqrtf(s), 1e-12f);
}

// ---------------------------------------------------------------------------
// 4) warp-MMA GEMM (fp16) + fused scaled softmax-dot epilogue.
//    CTA: M=128, N=256, 256 threads / 8 warps (2x4), warp tile 64x64.
//    K chunks of 64, 2-stage double buffer, 1 CTA/SM. grid (5, 128).
// ---------------------------------------------------------------------------
#define KC     64
#define NCH    (CF / KC)        // 16
#define SROW   144              // KC*2 + 16B pad
#define A_O    0
#define B_O    18432            // 128*144
#define STG    55296            // + 256*144
#define SMEM_DYN 139392         // max(2*STG=110592, Cs 128*264*4=135168) rounded up
#define CSTRIDE 264

__global__ void __launch_bounds__(256, 1) k_gemm_mma(float* __restrict__ out) {
    extern __shared__ __align__(128) char dsm[];
    const int tid   = threadIdx.x;
    const int wid   = tid >> 5;
    const int lane  = tid & 31;
    const int itile = blockIdx.x;
    const int b     = blockIdx.y;
    const int mw    = wid >> 2;           // 0..1 (64-row slice)
    const int nw    = wid & 3;            // 0..3 (64-col slice)

    const uint32_t sbase = smem_u32(dsm);

    const char* pA = (const char*)g_A + (size_t)(itile * 128) * CF * 2;
    const char* pB = (const char*)g_B + (size_t)b * RR * CF * 2;

    // ldmatrix A: 16x16 tiles at rows mw*64 + mi*16 (proven mapping)
    const uint32_t aoff = (uint32_t)((mw * 64 + (lane & 15)) * SROW + ((lane >> 4) << 4));
    // ldmatrix B x4 spanning two n8-blocks (proven mapping)
    const uint32_t boff = (uint32_t)((nw * 64 + ((lane >> 4) << 3) + (lane & 7)) * SROW
                                     + (((lane >> 3) & 1) << 4));

    float acc[4][8][4];
#pragma unroll
    for (int mi = 0; mi < 4; mi++)
#pragma unroll
        for (int ni = 0; ni < 8; ni++)
#pragma unroll
            for (int u = 0; u < 4; u++) acc[mi][ni][u] = 0.f;

    auto load_chunk = [&](int buf, int c) {
        const size_t kb = (size_t)c * (KC * 2);
        const uint32_t st = sbase + buf * STG;
        // A: 128 rows x 128B = 1024 xfers (4/thread)
#pragma unroll
        for (int it = 0; it < 4; it++) {
            int idx = tid + it * 256;
            int row = idx >> 3, j = idx & 7;
            CP_ASYNC16(st + A_O + row * SROW + j * 16,
                       pA + (size_t)row * (CF * 2) + kb + j * 16);
        }
        // B: 256 rows x 128B = 2048 xfers (8/thread)
#pragma unroll
        for (int it = 0; it < 8; it++) {
            int idx = tid + it * 256;
            int row = idx >> 3, j = idx & 7;
            CP_ASYNC16(st + B_O + row * SROW + j * 16,
                       pB + (size_t)row * (CF * 2) + kb + j * 16);
        }
    };

    load_chunk(0, 0); CP_COMMIT();

    for (int c = 0; c < NCH; c++) {
        const int buf = c & 1;
        CP_WAIT(0);            // chunk c arrived
        __syncthreads();       // buffer buf^1 free (computed at c-1)
        if (c + 1 < NCH) { load_chunk(buf ^ 1, c + 1); CP_COMMIT(); }

        const uint32_t st = sbase + buf * STG;
#pragma unroll
        for (int ks = 0; ks < 4; ks++) {
            const uint32_t kb = ks * 32;   // 16 fp16 = 32 bytes
            uint32_t a4[4][4];
#pragma unroll
            for (int mi = 0; mi < 4; mi++)
                ldsm4(a4[mi], st + A_O + aoff + mi * (16 * SROW) + kb);
#pragma unroll
            for (int p = 0; p < 4; p++) {
                uint32_t b4[4];
                ldsm4(b4, st + B_O + boff + p * (16 * SROW) + kb);
#pragma unroll
                for (int mi = 0; mi < 4; mi++) {
                    mma_fp16(acc[mi][2 * p],     a4[mi], b4);
                    mma_fp16(acc[mi][2 * p + 1], a4[mi], b4 + 2);
                }
            }
        }
    }
    __syncthreads();

    // ---- epilogue: accums -> smem C[128][CSTRIDE] ----
    float* Cs = (float*)dsm;
    const int n0 = nw * 64;
#pragma unroll
    for (int mi = 0; mi < 4; mi++)
#pragma unroll
        for (int ni = 0; ni < 8; ni++) {
            int r0 = mw * 64 + mi * 16 + (lane >> 2);
            int c0 = n0 + ni * 8 + 2 * (lane & 3);
            Cs[r0 * CSTRIDE + c0]           = acc[mi][ni][0];
            Cs[r0 * CSTRIDE + c0 + 1]       = acc[mi][ni][1];
            Cs[(r0 + 8) * CSTRIDE + c0]     = acc[mi][ni][2];
            Cs[(r0 + 8) * CSTRIDE + c0 + 1] = acc[mi][ni][3];
        }
    __syncthreads();

    // ---- scaled softmax-dot: 64 row-pairs, 8 per warp ----
    float sn[8];
#pragma unroll
    for (int u = 0; u < 8; u++) sn[u] = g_inorm[b * RR + lane + u * 32];

#pragma unroll
    for (int pp = 0; pp < 8; pp++) {
        int p = wid * 8 + pp;                  // 0..63
        const float* r1 = Cs + (2 * p) * CSTRIDE;
        const float* r2 = Cs + (2 * p + 1) * CSTRIDE;
        float l1[8], l2[8];
        float m = -INFINITY;
#pragma unroll
        for (int u = 0; u < 8; u++) {
            int r = lane + u * 32;
            l1[u] = r1[r] * sn[u];
            l2[u] = r2[r] * sn[u];
            m = fmaxf(m, l1[u]);
        }
#pragma unroll
        for (int off = 16; off; off >>= 1)
            m = fmaxf(m, __shfl_xor_sync(0xffffffffu, m, off));
        float se = 0.f, sd = 0.f;
#pragma unroll
        for (int u = 0; u < 8; u++) {
            float e = __expf(l1[u] - m);
            se += e;
            sd += e * l2[u];
        }
#pragma unroll
        for (int off = 16; off; off >>= 1) {
            se += __shfl_xor_sync(0xffffffffu, se, off);
            sd += __shfl_xor_sync(0xffffffffu, sd, off);
        }
        int i = itile * 64 + p;
        if (lane == 0 && i < NATT) out[b * NATT + i] = sd / se;
    }
}

// ---------------------------------------------------------------------------
extern "C" void kernel_launch(void* const* d_in, const int* in_sizes, int n_in,
                              void* d_out, int out_size) {
    const float* img = (const float*)d_in[0];
    const float* V   = (const float*)d_in[1];
    const float* W1  = (const float*)d_in[2];
    const float* W2  = (const float*)d_in[3];
    float* out = (float*)d_out;

    cudaFuncSetAttribute(k_gemm_mma, cudaFuncAttributeMaxDynamicSharedMemorySize, SMEM_DYN);

    k_qp<<<dim3(20, CF / 256, 2), 256>>>(V, W1, W2);
    k_conv<<<dim3(BB, 32), 256>>>(img);
    k_nred<<<BB, RR>>>();
    k_gemm_mma<<<dim3(5, BB), 256, SMEM_DYN>>>(out);
}

// round 12
// speedup vs baseline: 1.1689x; 1.1689x over previous
#include <cuda_runtime.h>
#include <cuda_fp16.h>
#include <math.h>
#include <stdint.h>

#define BB   128
#define CF   1024
#define RR   256
#define NATT 312
#define DV   300
#define NI   624
#define NIP  640

// ---------------- scratch (device globals) ----------------
__device__ __half g_A[NIP * CF];               // interleaved [2i]=Q_i,[2i+1]=P_i
__device__ __half g_B[(size_t)BB * CF * RR];   // [b][k][r] RAW img, fp16 (natural layout)
__device__ float  g_part[BB * 32 * RR];        // partial sumsq [b][kc][r]
__device__ float  g_inorm[BB * RR];            // 1 / max(||img[b,:,r]||, eps)

// ---------------- helpers ----------------
__device__ __forceinline__ uint32_t smem_u32(const void* p) {
    uint32_t a;
    asm("{ .reg .u64 t; cvta.to.shared.u64 t, %1; cvt.u32.u64 %0, t; }" : "=r"(a) : "l"(p));
    return a;
}
#define CP_ASYNC16(dst, src) \
    asm volatile("cp.async.cg.shared.global [%0], [%1], 16;" :: "r"(dst), "l"(src) : "memory")
#define CP_COMMIT() asm volatile("cp.async.commit_group;" ::: "memory")
#define CP_WAIT(N)  asm volatile("cp.async.wait_group %0;" :: "n"(N) : "memory")

__device__ __forceinline__ void ldsm4(uint32_t* r, uint32_t addr) {
    asm volatile("ldmatrix.sync.aligned.m8n8.x4.shared.b16 {%0,%1,%2,%3}, [%4];"
                 : "=r"(r[0]), "=r"(r[1]), "=r"(r[2]), "=r"(r[3]) : "r"(addr));
}
__device__ __forceinline__ void ldsm4t(uint32_t* r, uint32_t addr) {
    asm volatile("ldmatrix.sync.aligned.m8n8.x4.trans.shared.b16 {%0,%1,%2,%3}, [%4];"
                 : "=r"(r[0]), "=r"(r[1]), "=r"(r[2]), "=r"(r[3]) : "r"(addr));
}
__device__ __forceinline__ void mma_fp16(float* c, const uint32_t* a, const uint32_t* b) {
    asm volatile(
        "mma.sync.aligned.m16n8k16.row.col.f32.f16.f16.f32 "
        "{%0,%1,%2,%3}, {%4,%5,%6,%7}, {%8,%9}, {%0,%1,%2,%3};"
        : "+f"(c[0]), "+f"(c[1]), "+f"(c[2]), "+f"(c[3])
        : "r"(a[0]), "r"(a[1]), "r"(a[2]), "r"(a[3]), "r"(b[0]), "r"(b[1]));
}

// ---------------------------------------------------------------------------
// 1) QP rows: normalize V rows, multiply by W, interleave, single fp16.
// ---------------------------------------------------------------------------
__global__ void __launch_bounds__(256) k_qp(const float* __restrict__ V,
                                            const float* __restrict__ W1,
                                            const float* __restrict__ W2) {
    int i0 = blockIdx.x * 16;
    int z  = blockIdx.z;
    int j  = blockIdx.y * 256 + threadIdx.x;
    const float* W = z ? W2 : W1;

    __shared__ float vrow[16][DV];
    for (int t = threadIdx.x; t < 16 * DV; t += 256) {
        int ii = t / DV, k = t % DV;
        int gi = i0 + ii;
        vrow[ii][k] = (gi < NATT) ? V[gi * DV + k] : 0.f;
    }
    __syncthreads();
    {
        int w = threadIdx.x >> 5, lane = threadIdx.x & 31;
#pragma unroll
        for (int h = 0; h < 2; h++) {
            int row = 2 * w + h;
            float s = 0.f;
            for (int k = lane; k < DV; k += 32) { float v = vrow[row][k]; s += v * v; }
#pragma unroll
            for (int off = 16; off; off >>= 1) s += __shfl_xor_sync(0xffffffffu, s, off);
            float inv = 1.f / fmaxf(sqrtf(s), 1e-12f);
            for (int k = lane; k < DV; k += 32) vrow[row][k] *= inv;
        }
    }
    __syncthreads();

    float acc[16];
#pragma unroll
    for (int ii = 0; ii < 16; ii++) acc[ii] = 0.f;
    for (int k = 0; k < DV; k++) {
        float w = W[k * CF + j];
#pragma unroll
        for (int ii = 0; ii < 16; ii++) acc[ii] += vrow[ii][k] * w;
    }
#pragma unroll
    for (int ii = 0; ii < 16; ii++) {
        int row = 2 * (i0 + ii) + z;
        g_A[row * CF + j] = __float2half(acc[ii]);
    }
}

// ---------------------------------------------------------------------------
// 2) Streaming convert + norm-partials: NO transpose, NO smem.
//    grid (128 b, 32 kc), 256 threads (one per r). Fully coalesced.
// ---------------------------------------------------------------------------
__global__ void __launch_bounds__(256) k_conv(const float* __restrict__ img) {
    int b = blockIdx.x;
    int k0 = blockIdx.y * 32;
    int r = threadIdx.x;
    const float* src = img + ((size_t)b * CF + k0) * RR + r;
    __half*      dst = g_B + ((size_t)b * CF + k0) * RR + r;
    float s = 0.f;
#pragma unroll
    for (int k = 0; k < 32; k++) {
        float v = src[(size_t)k * RR];
        s += v * v;
        dst[(size_t)k * RR] = __float2half(v);
    }
    g_part[(b * 32 + blockIdx.y) * RR + r] = s;
}

// ---------------------------------------------------------------------------
// 3) reduce partials -> inorm
// ---------------------------------------------------------------------------
__global__ void __launch_bounds__(256) k_nred() {
    int b = blockIdx.x, r = threadIdx.x;
    float s = 0.f;
#pragma unroll
    for (int kc = 0; kc < 32; kc++) s += g_part[(b * 32 + kc) * RR + r];
    g_inorm[b * RR + r] = 1.f / fmaxf(sqrtf(s), 1e-12f);
}

// ---------------------------------------------------------------------------
// 4) warp-MMA GEMM (fp16) + fused scaled softmax-dot epilogue.  [R8 config]
//    CTA: M=64, N=256, 256 thr / 8 warps (2x4), warp tile 32x64, 2 CTA/SM.
//    B held k-major in smem, loaded with ldmatrix.trans.
// ---------------------------------------------------------------------------
#define KC     64
#define NCH    (CF / KC)        // 16
#define SROW   144              // A row: KC*2 + 16B pad
#define SROWB  528              // B row: RR*2 + 16B pad (k-major rows)
#define A_O    0
#define B_O    9216             // 64*144
#define STG    43008            // + 64*528
#define SMEM_DYN (2 * STG)      // 86016
#define CSTRIDE 264

__global__ void __launch_bounds__(256, 2) k_gemm_mma(float* __restrict__ out) {
    extern __shared__ __align__(128) char dsm[];
    const int tid   = threadIdx.x;
    const int wid   = tid >> 5;
    const int lane  = tid & 31;
    const int itile = blockIdx.x;
    const int b     = blockIdx.y;
    const int mw    = wid >> 2;           // 0..1
    const int nw    = wid & 3;            // 0..3

    const uint32_t sbase = smem_u32(dsm);

    const char* pA = (const char*)g_A + (size_t)(itile * 64) * CF * 2;
    const char* pB = (const char*)g_B + (size_t)b * CF * RR * 2;

    // ldmatrix A (proven): rows m, 16x16 tile
    const uint32_t aoff = (uint32_t)((mw * 32 + (lane & 15)) * SROW + ((lane >> 4) << 4));
    // ldmatrix.trans B from k-major rows:
    // lane l: k-row = (l>>3&1)*8 + (l&7); col bytes = (nw*64 + (l>>4)*8)*2
    const uint32_t boff = (uint32_t)((((lane >> 3) & 1) * 8 + (lane & 7)) * SROWB
                                     + (nw * 64 + ((lane >> 4) << 3)) * 2);

    float acc[2][8][4];
#pragma unroll
    for (int mi = 0; mi < 2; mi++)
#pragma unroll
        for (int ni = 0; ni < 8; ni++)
#pragma unroll
            for (int u = 0; u < 4; u++) acc[mi][ni][u] = 0.f;

    auto load_chunk = [&](int buf, int c) {
        const uint32_t st = sbase + buf * STG;
        // A: 64 m-rows x 128B = 512 xfers (2/thread); source row-major [m][k]
        const size_t kbA = (size_t)c * (KC * 2);
#pragma unroll
        for (int it = 0; it < 2; it++) {
            int idx = tid + it * 256;
            int row = idx >> 3, j = idx & 7;
            CP_ASYNC16(st + A_O + row * SROW + j * 16,
                       pA + (size_t)row * (CF * 2) + kbA + j * 16);
        }
        // B: 64 k-rows x 512B = 2048 xfers (8/thread); source [k][r], r contiguous
#pragma unroll
        for (int it = 0; it < 8; it++) {
            int idx = tid + it * 256;
            int row = idx >> 5, j = idx & 31;      // k-row 0..63, 16B piece 0..31
            CP_ASYNC16(st + B_O + row * SROWB + j * 16,
                       pB + (size_t)(c * KC + row) * (RR * 2) + j * 16);
        }
    };

    load_chunk(0, 0); CP_COMMIT();

    for (int c = 0; c < NCH; c++) {
        const int buf = c & 1;
        CP_WAIT(0);            // chunk c arrived
        __syncthreads();       // buffer buf^1 free
        if (c + 1 < NCH) { load_chunk(buf ^ 1, c + 1); CP_COMMIT(); }

        const uint32_t st = sbase + buf * STG;
#pragma unroll
        for (int ks = 0; ks < 4; ks++) {
            uint32_t a4[2][4];
#pragma unroll
            for (int mi = 0; mi < 2; mi++)
                ldsm4(a4[mi], st + A_O + aoff + mi * (16 * SROW) + ks * 32);
#pragma unroll
            for (int p = 0; p < 4; p++) {
                uint32_t b4[4];
                ldsm4t(b4, st + B_O + boff + ks * (16 * SROWB) + p * 32);
#pragma unroll
                for (int mi = 0; mi < 2; mi++) {
                    mma_fp16(acc[mi][2 * p],     a4[mi], b4);
                    mma_fp16(acc[mi][2 * p + 1], a4[mi], b4 + 2);
                }
            }
        }
    }
    __syncthreads();

    // ---- epilogue: accums -> smem C[64][CSTRIDE] ----
    float* Cs = (float*)dsm;
    const int n0 = nw * 64;
#pragma unroll
    for (int mi = 0; mi < 2; mi++)
#pragma unroll
        for (int ni = 0; ni < 8; ni++) {
            int r0 = mw * 32 + mi * 16 + (lane >> 2);
            int c0 = n0 + ni * 8 + 2 * (lane & 3);
            Cs[r0 * CSTRIDE + c0]           = acc[mi][ni][0];
            Cs[r0 * CSTRIDE + c0 + 1]       = acc[mi][ni][1];
            Cs[(r0 + 8) * CSTRIDE + c0]     = acc[mi][ni][2];
            Cs[(r0 + 8) * CSTRIDE + c0 + 1] = acc[mi][ni][3];
        }
    __syncthreads();

    // ---- scaled softmax-dot: 32 row-pairs, 4 per warp ----
    float sn[8];
#pragma unroll
    for (int u = 0; u < 8; u++) sn[u] = g_inorm[b * RR + lane + u * 32];

#pragma unroll
    for (int pp = 0; pp < 4; pp++) {
        int p = wid * 4 + pp;
        const float* r1 = Cs + (2 * p) * CSTRIDE;
        const float* r2 = Cs + (2 * p + 1) * CSTRIDE;
        float l1[8], l2[8];
        float m = -INFINITY;
#pragma unroll
        for (int u = 0; u < 8; u++) {
            int r = lane + u * 32;
            l1[u] = r1[r] * sn[u];
            l2[u] = r2[r] * sn[u];
            m = fmaxf(m, l1[u]);
        }
#pragma unroll
        for (int off = 16; off; off >>= 1)
            m = fmaxf(m, __shfl_xor_sync(0xffffffffu, m, off));
        float se = 0.f, sd = 0.f;
#pragma unroll
        for (int u = 0; u < 8; u++) {
            float e = __expf(l1[u] - m);
            se += e;
            sd += e * l2[u];
        }
#pragma unroll
        for (int off = 16; off; off >>= 1) {
            se += __shfl_xor_sync(0xffffffffu, se, off);
            sd += __shfl_xor_sync(0xffffffffu, sd, off);
        }
        int i = itile * 32 + p;
        if (lane == 0 && i < NATT) out[b * NATT + i] = sd / se;
    }
}

// ---------------------------------------------------------------------------
extern "C" void kernel_launch(void* const* d_in, const int* in_sizes, int n_in,
                              void* d_out, int out_size) {
    const float* img = (const float*)d_in[0];
    const float* V   = (const float*)d_in[1];
    const float* W1  = (const float*)d_in[2];
    const float* W2  = (const float*)d_in[3];
    float* out = (float*)d_out;

    cudaFuncSetAttribute(k_gemm_mma, cudaFuncAttributeMaxDynamicSharedMemorySize, SMEM_DYN);

    k_qp<<<dim3(20, CF / 256, 2), 256>>>(V, W1, W2);
    k_conv<<<dim3(BB, 32), 256>>>(img);
    k_nred<<<BB, RR>>>();
    k_gemm_mma<<<dim3(10, BB), 256, SMEM_DYN>>>(out);
}

// round 13
// speedup vs baseline: 1.2025x; 1.0287x over previous
#include <cuda_runtime.h>
#include <cuda_fp16.h>
#include <math.h>
#include <stdint.h>

#define BB   128
#define CF   1024
#define RR   256
#define NATT 312
#define DV   300
#define NI   624
#define NIP  640

#define NCONV 2048               // 128 b * 16 kc   (64 k-rows per block)
#define NQP   160                // 20 * 4 * 2

// ---------------- scratch (device globals) ----------------
__device__ __half g_A[NIP * CF];               // interleaved [2i]=Q_i,[2i+1]=P_i
__device__ __half g_B[(size_t)BB * CF * RR];   // [b][k][r] RAW img, fp16
__device__ float  g_part[BB * 16 * RR];        // partial sumsq [b][kc][r]
__device__ float  g_inorm[BB * RR];            // 1 / max(||img[b,:,r]||, eps)

// ---------------- helpers ----------------
__device__ __forceinline__ uint32_t smem_u32(const void* p) {
    uint32_t a;
    asm("{ .reg .u64 t; cvta.to.shared.u64 t, %1; cvt.u32.u64 %0, t; }" : "=r"(a) : "l"(p));
    return a;
}
#define CP_ASYNC16(dst, src) \
    asm volatile("cp.async.cg.shared.global [%0], [%1], 16;" :: "r"(dst), "l"(src) : "memory")
#define CP_COMMIT() asm volatile("cp.async.commit_group;" ::: "memory")
#define CP_WAIT(N)  asm volatile("cp.async.wait_group %0;" :: "n"(N) : "memory")

__device__ __forceinline__ void ldsm4(uint32_t* r, uint32_t addr) {
    asm volatile("ldmatrix.sync.aligned.m8n8.x4.shared.b16 {%0,%1,%2,%3}, [%4];"
                 : "=r"(r[0]), "=r"(r[1]), "=r"(r[2]), "=r"(r[3]) : "r"(addr));
}
__device__ __forceinline__ void ldsm4t(uint32_t* r, uint32_t addr) {
    asm volatile("ldmatrix.sync.aligned.m8n8.x4.trans.shared.b16 {%0,%1,%2,%3}, [%4];"
                 : "=r"(r[0]), "=r"(r[1]), "=r"(r[2]), "=r"(r[3]) : "r"(addr));
}
__device__ __forceinline__ void mma_fp16(float* c, const uint32_t* a, const uint32_t* b) {
    asm volatile(
        "mma.sync.aligned.m16n8k16.row.col.f32.f16.f16.f32 "
        "{%0,%1,%2,%3}, {%4,%5,%6,%7}, {%8,%9}, {%0,%1,%2,%3};"
        : "+f"(c[0]), "+f"(c[1]), "+f"(c[2]), "+f"(c[3])
        : "r"(a[0]), "r"(a[1]), "r"(a[2]), "r"(a[3]), "r"(b[0]), "r"(b[1]));
}

// ---------------------------------------------------------------------------
// 1) Fused prep kernel: blocks [0, NCONV) stream-convert img (+norm partials);
//    blocks [NCONV, NCONV+NQP) compute QP rows. Independent work, one launch.
// ---------------------------------------------------------------------------
__global__ void __launch_bounds__(256) k_prep(const float* __restrict__ img,
                                              const float* __restrict__ V,
                                              const float* __restrict__ W1,
                                              const float* __restrict__ W2) {
    __shared__ float sm[16 * DV];     // qp: vrow[16][DV]; conv: sp[4][64][4]
    const int tid = threadIdx.x;

    if (blockIdx.x < NCONV) {
        // ---- conv: img[b][k0..k0+64][*] -> g_B fp16 + sumsq partials ----
        const int b  = blockIdx.x >> 4;
        const int kc = blockIdx.x & 15;
        const int kg = tid >> 6;                 // 0..3  (k offset group)
        const int q  = tid & 63;                 // r-quad 0..63
        const float4* src = (const float4*)(img + ((size_t)b * CF + kc * 64) * RR) + q;
        __half2* dst = (__half2*)(g_B + ((size_t)b * CF + kc * 64) * RR) + 2 * q;

        float s0 = 0.f, s1 = 0.f, s2 = 0.f, s3 = 0.f;
#pragma unroll
        for (int j = 0; j < 16; j++) {
            int k = j * 4 + kg;
            float4 v = src[(size_t)k * (RR / 4)];
            s0 += v.x * v.x; s1 += v.y * v.y; s2 += v.z * v.z; s3 += v.w * v.w;
            dst[(size_t)k * (RR / 2)]     = __floats2half2_rn(v.x, v.y);
            dst[(size_t)k * (RR / 2) + 1] = __floats2half2_rn(v.z, v.w);
        }
        float (*sp)[64][4] = (float (*)[64][4])sm;
        sp[kg][q][0] = s0; sp[kg][q][1] = s1; sp[kg][q][2] = s2; sp[kg][q][3] = s3;
        __syncthreads();
        if (kg == 0) {
            float4 o;
            o.x = sp[0][q][0] + sp[1][q][0] + sp[2][q][0] + sp[3][q][0];
            o.y = sp[0][q][1] + sp[1][q][1] + sp[2][q][1] + sp[3][q][1];
            o.z = sp[0][q][2] + sp[1][q][2] + sp[2][q][2] + sp[3][q][2];
            o.w = sp[0][q][3] + sp[1][q][3] + sp[2][q][3] + sp[3][q][3];
            *(float4*)&g_part[((size_t)b * 16 + kc) * RR + 4 * q] = o;
        }
        return;
    }

    // ---- qp: normalize V rows, multiply by W, interleave, fp16 ----
    const int qb = blockIdx.x - NCONV;           // 0..159
    const int i0 = (qb % 20) * 16;
    const int jy = (qb / 20) & 3;
    const int z  = qb / 80;
    const int j  = jy * 256 + tid;
    const float* W = z ? W2 : W1;

    float (*vrow)[DV] = (float (*)[DV])sm;
    for (int t = tid; t < 16 * DV; t += 256) {
        int ii = t / DV, k = t % DV;
        int gi = i0 + ii;
        vrow[ii][k] = (gi < NATT) ? V[gi * DV + k] : 0.f;
    }
    __syncthreads();
    {
        int w = tid >> 5, lane = tid & 31;
#pragma unroll
        for (int h = 0; h < 2; h++) {
            int row = 2 * w + h;
            float s = 0.f;
            for (int k = lane; k < DV; k += 32) { float v = vrow[row][k]; s += v * v; }
#pragma unroll
            for (int off = 16; off; off >>= 1) s += __shfl_xor_sync(0xffffffffu, s, off);
            float inv = 1.f / fmaxf(sqrtf(s), 1e-12f);
            for (int k = lane; k < DV; k += 32) vrow[row][k] *= inv;
        }
    }
    __syncthreads();

    float acc[16];
#pragma unroll
    for (int ii = 0; ii < 16; ii++) acc[ii] = 0.f;
    for (int k = 0; k < DV; k++) {
        float w = W[k * CF + j];
#pragma unroll
        for (int ii = 0; ii < 16; ii++) acc[ii] += vrow[ii][k] * w;
    }
#pragma unroll
    for (int ii = 0; ii < 16; ii++) {
        int row = 2 * (i0 + ii) + z;
        g_A[row * CF + j] = __float2half(acc[ii]);
    }
}

// ---------------------------------------------------------------------------
// 2) reduce partials -> inorm
// ---------------------------------------------------------------------------
__global__ void __launch_bounds__(256) k_nred() {
    int b = blockIdx.x, r = threadIdx.x;
    float s = 0.f;
#pragma unroll
    for (int kc = 0; kc < 16; kc++) s += g_part[((size_t)b * 16 + kc) * RR + r];
    g_inorm[b * RR + r] = 1.f / fmaxf(sqrtf(s), 1e-12f);
}

// ---------------------------------------------------------------------------
// 3) warp-MMA GEMM (fp16) + fused scaled softmax-dot epilogue.  [R12, proven]
// ---------------------------------------------------------------------------
#define KC     64
#define NCH    (CF / KC)        // 16
#define SROW   144              // A row: KC*2 + 16B pad
#define SROWB  528              // B row: RR*2 + 16B pad (k-major rows)
#define A_O    0
#define B_O    9216             // 64*144
#define STG    43008            // + 64*528
#define SMEM_DYN (2 * STG)      // 86016
#define CSTRIDE 264

__global__ void __launch_bounds__(256, 2) k_gemm_mma(float* __restrict__ out) {
    extern __shared__ __align__(128) char dsm[];
    const int tid   = threadIdx.x;
    const int wid   = tid >> 5;
    const int lane  = tid & 31;
    const int itile = blockIdx.x;
    const int b     = blockIdx.y;
    const int mw    = wid >> 2;           // 0..1
    const int nw    = wid & 3;            // 0..3

    const uint32_t sbase = smem_u32(dsm);

    const char* pA = (const char*)g_A + (size_t)(itile * 64) * CF * 2;
    const char* pB = (const char*)g_B + (size_t)b * CF * RR * 2;

    const uint32_t aoff = (uint32_t)((mw * 32 + (lane & 15)) * SROW + ((lane >> 4) << 4));
    const uint32_t boff = (uint32_t)((((lane >> 3) & 1) * 8 + (lane & 7)) * SROWB
                                     + (nw * 64 + ((lane >> 4) << 3)) * 2);

    float acc[2][8][4];
#pragma unroll
    for (int mi = 0; mi < 2; mi++)
#pragma unroll
        for (int ni = 0; ni < 8; ni++)
#pragma unroll
            for (int u = 0; u < 4; u++) acc[mi][ni][u] = 0.f;

    auto load_chunk = [&](int buf, int c) {
        const uint32_t st = sbase + buf * STG;
        const size_t kbA = (size_t)c * (KC * 2);
#pragma unroll
        for (int it = 0; it < 2; it++) {
            int idx = tid + it * 256;
            int row = idx >> 3, j = idx & 7;
            CP_ASYNC16(st + A_O + row * SROW + j * 16,
                       pA + (size_t)row * (CF * 2) + kbA + j * 16);
        }
#pragma unroll
        for (int it = 0; it < 8; it++) {
            int idx = tid + it * 256;
            int row = idx >> 5, j = idx & 31;
            CP_ASYNC16(st + B_O + row * SROWB + j * 16,
                       pB + (size_t)(c * KC + row) * (RR * 2) + j * 16);
        }
    };

    load_chunk(0, 0); CP_COMMIT();

    for (int c = 0; c < NCH; c++) {
        const int buf = c & 1;
        CP_WAIT(0);
        __syncthreads();
        if (c + 1 < NCH) { load_chunk(buf ^ 1, c + 1); CP_COMMIT(); }

        const uint32_t st = sbase + buf * STG;
#pragma unroll
        for (int ks = 0; ks < 4; ks++) {
            uint32_t a4[2][4];
#pragma unroll
            for (int mi = 0; mi < 2; mi++)
                ldsm4(a4[mi], st + A_O + aoff + mi * (16 * SROW) + ks * 32);
#pragma unroll
            for (int p = 0; p < 4; p++) {
                uint32_t b4[4];
                ldsm4t(b4, st + B_O + boff + ks * (16 * SROWB) + p * 32);
#pragma unroll
                for (int mi = 0; mi < 2; mi++) {
                    mma_fp16(acc[mi][2 * p],     a4[mi], b4);
                    mma_fp16(acc[mi][2 * p + 1], a4[mi], b4 + 2);
                }
            }
        }
    }
    __syncthreads();

    float* Cs = (float*)dsm;
    const int n0 = nw * 64;
#pragma unroll
    for (int mi = 0; mi < 2; mi++)
#pragma unroll
        for (int ni = 0; ni < 8; ni++) {
            int r0 = mw * 32 + mi * 16 + (lane >> 2);
            int c0 = n0 + ni * 8 + 2 * (lane & 3);
            Cs[r0 * CSTRIDE + c0]           = acc[mi][ni][0];
            Cs[r0 * CSTRIDE + c0 + 1]       = acc[mi][ni][1];
            Cs[(r0 + 8) * CSTRIDE + c0]     = acc[mi][ni][2];
            Cs[(r0 + 8) * CSTRIDE + c0 + 1] = acc[mi][ni][3];
        }
    __syncthreads();

    float sn[8];
#pragma unroll
    for (int u = 0; u < 8; u++) sn[u] = g_inorm[b * RR + lane + u * 32];

#pragma unroll
    for (int pp = 0; pp < 4; pp++) {
        int p = wid * 4 + pp;
        const float* r1 = Cs + (2 * p) * CSTRIDE;
        const float* r2 = Cs + (2 * p + 1) * CSTRIDE;
        float l1[8], l2[8];
        float m = -INFINITY;
#pragma unroll
        for (int u = 0; u < 8; u++) {
            int r = lane + u * 32;
            l1[u] = r1[r] * sn[u];
            l2[u] = r2[r] * sn[u];
            m = fmaxf(m, l1[u]);
        }
#pragma unroll
        for (int off = 16; off; off >>= 1)
            m = fmaxf(m, __shfl_xor_sync(0xffffffffu, m, off));
        float se = 0.f, sd = 0.f;
#pragma unroll
        for (int u = 0; u < 8; u++) {
            float e = __expf(l1[u] - m);
            se += e;
            sd += e * l2[u];
        }
#pragma unroll
        for (int off = 16; off; off >>= 1) {
            se += __shfl_xor_sync(0xffffffffu, se, off);
            sd += __shfl_xor_sync(0xffffffffu, sd, off);
        }
        int i = itile * 32 + p;
        if (lane == 0 && i < NATT) out[b * NATT + i] = sd / se;
    }
}

// ---------------------------------------------------------------------------
extern "C" void kernel_launch(void* const* d_in, const int* in_sizes, int n_in,
                              void* d_out, int out_size) {
    const float* img = (const float*)d_in[0];
    const float* V   = (const float*)d_in[1];
    const float* W1  = (const float*)d_in[2];
    const float* W2  = (const float*)d_in[3];
    float* out = (float*)d_out;

    cudaFuncSetAttribute(k_gemm_mma, cudaFuncAttributeMaxDynamicSharedMemorySize, SMEM_DYN);

    k_prep<<<NCONV + NQP, 256>>>(img, V, W1, W2);
    k_nred<<<BB, RR>>>();
    k_gemm_mma<<<dim3(10, BB), 256, SMEM_DYN>>>(out);
}

// round 14
// speedup vs baseline: 1.2426x; 1.0334x over previous
#include <cuda_runtime.h>
#include <cuda_fp16.h>
#include <math.h>
#include <stdint.h>

#define BB   128
#define CF   1024
#define RR   256
#define NATT 312
#define DV   300
#define NI   624
#define NIP  640

// ---------------- scratch (device globals) ----------------
__device__ __half g_A[NIP * CF];               // interleaved [2i]=Q_i,[2i+1]=P_i
__device__ __half g_B[(size_t)BB * CF * RR];   // [b][k][r] RAW img, fp16
__device__ float  g_part[(size_t)BB * 64 * RR];// partial sumsq [b][64][r]
__device__ float  g_inorm[BB * RR];            // 1 / max(||img[b,:,r]||, eps)

// ---------------- helpers ----------------
__device__ __forceinline__ uint32_t smem_u32(const void* p) {
    uint32_t a;
    asm("{ .reg .u64 t; cvta.to.shared.u64 t, %1; cvt.u32.u64 %0, t; }" : "=r"(a) : "l"(p));
    return a;
}
#define CP_ASYNC16(dst, src) \
    asm volatile("cp.async.cg.shared.global [%0], [%1], 16;" :: "r"(dst), "l"(src) : "memory")
#define CP_COMMIT() asm volatile("cp.async.commit_group;" ::: "memory")
#define CP_WAIT(N)  asm volatile("cp.async.wait_group %0;" :: "n"(N) : "memory")

__device__ __forceinline__ void ldsm4(uint32_t* r, uint32_t addr) {
    asm volatile("ldmatrix.sync.aligned.m8n8.x4.shared.b16 {%0,%1,%2,%3}, [%4];"
                 : "=r"(r[0]), "=r"(r[1]), "=r"(r[2]), "=r"(r[3]) : "r"(addr));
}
__device__ __forceinline__ void ldsm4t(uint32_t* r, uint32_t addr) {
    asm volatile("ldmatrix.sync.aligned.m8n8.x4.trans.shared.b16 {%0,%1,%2,%3}, [%4];"
                 : "=r"(r[0]), "=r"(r[1]), "=r"(r[2]), "=r"(r[3]) : "r"(addr));
}
__device__ __forceinline__ void mma_fp16(float* c, const uint32_t* a, const uint32_t* b) {
    asm volatile(
        "mma.sync.aligned.m16n8k16.row.col.f32.f16.f16.f32 "
        "{%0,%1,%2,%3}, {%4,%5,%6,%7}, {%8,%9}, {%0,%1,%2,%3};"
        : "+f"(c[0]), "+f"(c[1]), "+f"(c[2]), "+f"(c[3])
        : "r"(a[0]), "r"(a[1]), "r"(a[2]), "r"(a[3]), "r"(b[0]), "r"(b[1]));
}

// ---------------------------------------------------------------------------
// 1) Streaming convert + per-thread norm partials. NO smem, NO sync.
//    grid (128 b, 16 kc), 256 threads. Thread: r-quad q, k-group kg, 16 ks.
// ---------------------------------------------------------------------------
__global__ void __launch_bounds__(256) k_conv(const float* __restrict__ img) {
    const int b  = blockIdx.x;
    const int kc = blockIdx.y;               // 0..15
    const int kg = threadIdx.x >> 6;         // 0..3
    const int q  = threadIdx.x & 63;         // r-quad 0..63
    const float4* src = (const float4*)(img + ((size_t)b * CF + kc * 64) * RR) + q;
    __half2* dst = (__half2*)(g_B + ((size_t)b * CF + kc * 64) * RR) + 2 * q;

    float s0 = 0.f, s1 = 0.f, s2 = 0.f, s3 = 0.f;
#pragma unroll
    for (int j = 0; j < 16; j++) {
        int k = j * 4 + kg;
        float4 v = src[(size_t)k * (RR / 4)];
        s0 += v.x * v.x; s1 += v.y * v.y; s2 += v.z * v.z; s3 += v.w * v.w;
        dst[(size_t)k * (RR / 2)]     = __floats2half2_rn(v.x, v.y);
        dst[(size_t)k * (RR / 2) + 1] = __floats2half2_rn(v.z, v.w);
    }
    float4 o = make_float4(s0, s1, s2, s3);
    *(float4*)&g_part[(((size_t)b * 16 + kc) * 4 + kg) * RR + 4 * q] = o;
}

// ---------------------------------------------------------------------------
// 2) QP rows: 8 rows/block, unroll-4 pipelined k-loop. grid (40, 4, 2).
// ---------------------------------------------------------------------------
__global__ void __launch_bounds__(256) k_qp(const float* __restrict__ V,
                                            const float* __restrict__ W1,
                                            const float* __restrict__ W2) {
    int i0 = blockIdx.x * 8;
    int z  = blockIdx.z;
    int j  = blockIdx.y * 256 + threadIdx.x;
    const float* W = z ? W2 : W1;

    __shared__ float vrow[8][DV];
    for (int t = threadIdx.x; t < 8 * DV; t += 256) {
        int ii = t / DV, k = t % DV;
        int gi = i0 + ii;
        vrow[ii][k] = (gi < NATT) ? V[gi * DV + k] : 0.f;
    }
    __syncthreads();
    {
        int w = threadIdx.x >> 5, lane = threadIdx.x & 31;
        float s = 0.f;
        for (int k = lane; k < DV; k += 32) { float v = vrow[w][k]; s += v * v; }
#pragma unroll
        for (int off = 16; off; off >>= 1) s += __shfl_xor_sync(0xffffffffu, s, off);
        float inv = 1.f / fmaxf(sqrtf(s), 1e-12f);
        for (int k = lane; k < DV; k += 32) vrow[w][k] *= inv;
    }
    __syncthreads();

    float acc[8] = {0, 0, 0, 0, 0, 0, 0, 0};
#pragma unroll 4
    for (int k = 0; k < DV; k++) {
        float w = W[k * CF + j];
#pragma unroll
        for (int ii = 0; ii < 8; ii++) acc[ii] += vrow[ii][k] * w;
    }
#pragma unroll
    for (int ii = 0; ii < 8; ii++) {
        int row = 2 * (i0 + ii) + z;
        g_A[row * CF + j] = __float2half(acc[ii]);
    }
}

// ---------------------------------------------------------------------------
// 3) reduce 64 partials -> inorm. grid BB, block 256.
// ---------------------------------------------------------------------------
__global__ void __launch_bounds__(256) k_nred() {
    int b = blockIdx.x, r = threadIdx.x;
    float s = 0.f;
#pragma unroll 8
    for (int p = 0; p < 64; p++) s += g_part[((size_t)b * 64 + p) * RR + r];
    g_inorm[b * RR + r] = 1.f / fmaxf(sqrtf(s), 1e-12f);
}

// ---------------------------------------------------------------------------
// 4) warp-MMA GEMM (fp16) + fused scaled softmax-dot epilogue. [R12, proven]
// ---------------------------------------------------------------------------
#define KC     64
#define NCH    (CF / KC)        // 16
#define SROW   144              // A row: KC*2 + 16B pad
#define SROWB  528              // B row: RR*2 + 16B pad (k-major rows)
#define A_O    0
#define B_O    9216             // 64*144
#define STG    43008            // + 64*528
#define SMEM_DYN (2 * STG)      // 86016
#define CSTRIDE 264

__global__ void __launch_bounds__(256, 2) k_gemm_mma(float* __restrict__ out) {
    extern __shared__ __align__(128) char dsm[];
    const int tid   = threadIdx.x;
    const int wid   = tid >> 5;
    const int lane  = tid & 31;
    const int itile = blockIdx.x;
    const int b     = blockIdx.y;
    const int mw    = wid >> 2;           // 0..1
    const int nw    = wid & 3;            // 0..3

    const uint32_t sbase = smem_u32(dsm);

    const char* pA = (const char*)g_A + (size_t)(itile * 64) * CF * 2;
    const char* pB = (const char*)g_B + (size_t)b * CF * RR * 2;

    const uint32_t aoff = (uint32_t)((mw * 32 + (lane & 15)) * SROW + ((lane >> 4) << 4));
    const uint32_t boff = (uint32_t)((((lane >> 3) & 1) * 8 + (lane & 7)) * SROWB
                                     + (nw * 64 + ((lane >> 4) << 3)) * 2);

    float acc[2][8][4];
#pragma unroll
    for (int mi = 0; mi < 2; mi++)
#pragma unroll
        for (int ni = 0; ni < 8; ni++)
#pragma unroll
            for (int u = 0; u < 4; u++) acc[mi][ni][u] = 0.f;

    auto load_chunk = [&](int buf, int c) {
        const uint32_t st = sbase + buf * STG;
        const size_t kbA = (size_t)c * (KC * 2);
#pragma unroll
        for (int it = 0; it < 2; it++) {
            int idx = tid + it * 256;
            int row = idx >> 3, j = idx & 7;
            CP_ASYNC16(st + A_O + row * SROW + j * 16,
                       pA + (size_t)row * (CF * 2) + kbA + j * 16);
        }
#pragma unroll
        for (int it = 0; it < 8; it++) {
            int idx = tid + it * 256;
            int row = idx >> 5, j = idx & 31;
            CP_ASYNC16(st + B_O + row * SROWB + j * 16,
                       pB + (size_t)(c * KC + row) * (RR * 2) + j * 16);
        }
    };

    load_chunk(0, 0); CP_COMMIT();

    for (int c = 0; c < NCH; c++) {
        const int buf = c & 1;
        CP_WAIT(0);
        __syncthreads();
        if (c + 1 < NCH) { load_chunk(buf ^ 1, c + 1); CP_COMMIT(); }

        const uint32_t st = sbase + buf * STG;
#pragma unroll
        for (int ks = 0; ks < 4; ks++) {
            uint32_t a4[2][4];
#pragma unroll
            for (int mi = 0; mi < 2; mi++)
                ldsm4(a4[mi], st + A_O + aoff + mi * (16 * SROW) + ks * 32);
#pragma unroll
            for (int p = 0; p < 4; p++) {
                uint32_t b4[4];
                ldsm4t(b4, st + B_O + boff + ks * (16 * SROWB) + p * 32);
#pragma unroll
                for (int mi = 0; mi < 2; mi++) {
                    mma_fp16(acc[mi][2 * p],     a4[mi], b4);
                    mma_fp16(acc[mi][2 * p + 1], a4[mi], b4 + 2);
                }
            }
        }
    }
    __syncthreads();

    float* Cs = (float*)dsm;
    const int n0 = nw * 64;
#pragma unroll
    for (int mi = 0; mi < 2; mi++)
#pragma unroll
        for (int ni = 0; ni < 8; ni++) {
            int r0 = mw * 32 + mi * 16 + (lane >> 2);
            int c0 = n0 + ni * 8 + 2 * (lane & 3);
            Cs[r0 * CSTRIDE + c0]           = acc[mi][ni][0];
            Cs[r0 * CSTRIDE + c0 + 1]       = acc[mi][ni][1];
            Cs[(r0 + 8) * CSTRIDE + c0]     = acc[mi][ni][2];
            Cs[(r0 + 8) * CSTRIDE + c0 + 1] = acc[mi][ni][3];
        }
    __syncthreads();

    float sn[8];
#pragma unroll
    for (int u = 0; u < 8; u++) sn[u] = g_inorm[b * RR + lane + u * 32];

#pragma unroll
    for (int pp = 0; pp < 4; pp++) {
        int p = wid * 4 + pp;
        const float* r1 = Cs + (2 * p) * CSTRIDE;
        const float* r2 = Cs + (2 * p + 1) * CSTRIDE;
        float l1[8], l2[8];
        float m = -INFINITY;
#pragma unroll
        for (int u = 0; u < 8; u++) {
            int r = lane + u * 32;
            l1[u] = r1[r] * sn[u];
            l2[u] = r2[r] * sn[u];
            m = fmaxf(m, l1[u]);
        }
#pragma unroll
        for (int off = 16; off; off >>= 1)
            m = fmaxf(m, __shfl_xor_sync(0xffffffffu, m, off));
        float se = 0.f, sd = 0.f;
#pragma unroll
        for (int u = 0; u < 8; u++) {
            float e = __expf(l1[u] - m);
            se += e;
            sd += e * l2[u];
        }
#pragma unroll
        for (int off = 16; off; off >>= 1) {
            se += __shfl_xor_sync(0xffffffffu, se, off);
            sd += __shfl_xor_sync(0xffffffffu, sd, off);
        }
        int i = itile * 32 + p;
        if (lane == 0 && i < NATT) out[b * NATT + i] = sd / se;
    }
}

// ---------------------------------------------------------------------------
extern "C" void kernel_launch(void* const* d_in, const int* in_sizes, int n_in,
                              void* d_out, int out_size) {
    const float* img = (const float*)d_in[0];
    const float* V   = (const float*)d_in[1];
    const float* W1  = (const float*)d_in[2];
    const float* W2  = (const float*)d_in[3];
    float* out = (float*)d_out;

    cudaFuncSetAttribute(k_gemm_mma, cudaFuncAttributeMaxDynamicSharedMemorySize, SMEM_DYN);

    k_conv<<<dim3(BB, 16), 256>>>(img);
    k_qp<<<dim3(40, 4, 2), 256>>>(V, W1, W2);
    k_nred<<<BB, RR>>>();
    k_gemm_mma<<<dim3(10, BB), 256, SMEM_DYN>>>(out);
}